// round 14
// baseline (speedup 1.0000x reference)
#include <cuda_runtime.h>
#include <math.h>

// Dataset-fixed shapes: r is [16, 2048, 3] fp32
#define NPTS    1024              // points per MST problem
#define NPROB   32                // independent MST problems
#define THREADS 256               // 8 warps: TWO per SMSP (stall interleaving)
#define PPT     (NPTS / THREADS)  // 4 points per thread
#define NPAIR   (PPT / 2)         // 2 f32x2 pairs per thread
#define NW      (THREADS / 32)    // 8 warps

__device__ float    g_partials[NPROB];
__device__ unsigned g_ticket;     // zero-init; last CTA resets for graph replay

__device__ __forceinline__ float warp_sum(float v) {
#pragma unroll
    for (int o = 16; o; o >>= 1) v += __shfl_xor_sync(0xffffffffu, v, o);
    return v;
}

__device__ __forceinline__ unsigned um(unsigned a, unsigned b) { return a < b ? a : b; }

// ---- packed f32x2 helpers (Blackwell FFMA2/FADD2 via PTX) ----
__device__ __forceinline__ unsigned long long pack2(float lo, float hi) {
    unsigned long long d;
    asm("mov.b64 %0, {%1, %2};" : "=l"(d) : "f"(lo), "f"(hi));
    return d;
}
__device__ __forceinline__ void unpack2u(unsigned& lo, unsigned& hi, unsigned long long v) {
    asm("mov.b64 {%0, %1}, %2;" : "=r"(lo), "=r"(hi) : "l"(v));
}
__device__ __forceinline__ unsigned long long add2(unsigned long long a, unsigned long long b) {
    unsigned long long d;
    asm("add.rn.f32x2 %0, %1, %2;" : "=l"(d) : "l"(a), "l"(b));
    return d;
}
__device__ __forceinline__ unsigned long long fma2(unsigned long long a, unsigned long long b,
                                                   unsigned long long c) {
    unsigned long long d;
    asm("fma.rn.f32x2 %0, %1, %2, %3;" : "=l"(d) : "l"(a), "l"(b), "l"(c));
    return d;
}

// Pack: high 22 bits = float bits of h = d^2/2 (low 10 mantissa bits truncated),
// low 10 bits = point index. Unsigned order == (h, idx) order (h >= 0).
// pk values are globally unique within a problem (index embedded).
#define PK_MASK 0xFFFFFC00u

__global__ __launch_bounds__(THREADS, 1)
void topo_mst_kernel(const float* __restrict__ r, float* __restrict__ out)
{
    // Pre-duplicated point data: entry 2i = {x,x | y,y}, 2i+1 = {z,z | q,q}.
    __shared__ ulonglong2 pts2[2 * NPTS];           // 32 KB
    __shared__ float redbuf[3][NW];
    __shared__ alignas(16) unsigned s_pk[2][NW];    // double-buffered warp mins
    __shared__ bool s_last;

    const int tid  = threadIdx.x;
    const int lane = tid & 31;
    const int wid  = tid >> 5;

    const float* base = r + (size_t)blockIdx.x * NPTS * 3;

    // ---- Load (thread t owns points t, t+256, t+512, t+768) ----
    float lx[PPT], ly[PPT], lz[PPT];
    float sx = 0.f, sy = 0.f, sz = 0.f;
#pragma unroll
    for (int s = 0; s < PPT; s++) {
        int i = tid + s * THREADS;
        float x = base[3 * i + 0];
        float y = base[3 * i + 1];
        float z = base[3 * i + 2];
        lx[s] = x; ly[s] = y; lz[s] = z;
        sx += x; sy += y; sz += z;
    }

    // ---- Mean ----
    sx = warp_sum(sx); sy = warp_sum(sy); sz = warp_sum(sz);
    if (lane == 0) { redbuf[0][wid] = sx; redbuf[1][wid] = sy; redbuf[2][wid] = sz; }
    __syncthreads();
    float mx = 0.f, my = 0.f, mz = 0.f;
#pragma unroll
    for (int w = 0; w < NW; w++) { mx += redbuf[0][w]; my += redbuf[1][w]; mz += redbuf[2][w]; }
    mx *= (1.0f / NPTS); my *= (1.0f / NPTS); mz *= (1.0f / NPTS);
    __syncthreads();

    // ---- Variance ----
    float vx = 0.f, vy = 0.f, vz = 0.f;
#pragma unroll
    for (int s = 0; s < PPT; s++) {
        float dx = lx[s] - mx, dy = ly[s] - my, dz = lz[s] - mz;
        vx = fmaf(dx, dx, vx); vy = fmaf(dy, dy, vy); vz = fmaf(dz, dz, vz);
    }
    vx = warp_sum(vx); vy = warp_sum(vy); vz = warp_sum(vz);
    if (lane == 0) { redbuf[0][wid] = vx; redbuf[1][wid] = vy; redbuf[2][wid] = vz; }
    __syncthreads();
    vx = 0.f; vy = 0.f; vz = 0.f;
#pragma unroll
    for (int w = 0; w < NW; w++) { vx += redbuf[0][w]; vy += redbuf[1][w]; vz += redbuf[2][w]; }
    const float inx = 1.0f / (sqrtf(vx * (1.0f / NPTS)) + 1e-8f);
    const float iny = 1.0f / (sqrtf(vy * (1.0f / NPTS)) + 1e-8f);
    const float inz = 1.0f / (sqrtf(vz * (1.0f / NPTS)) + 1e-8f);

    // ---- Normalize; q = |p|^2/2; duplicated shared pairs; packed state ----
    unsigned long long nx2[NPAIR], ny2[NPAIR], nz2[NPAIR], q2[NPAIR];
    {
        float ql[PPT];
#pragma unroll
        for (int s = 0; s < PPT; s++) {
            int i = tid + s * THREADS;
            float x = (lx[s] - mx) * inx;
            float y = (ly[s] - my) * iny;
            float z = (lz[s] - mz) * inz;
            lx[s] = x; ly[s] = y; lz[s] = z;
            ql[s] = 0.5f * fmaf(x, x, fmaf(y, y, z * z));
            ulonglong2 e0, e1;
            e0.x = pack2(x, x);    e0.y = pack2(y, y);
            e1.x = pack2(z, z);    e1.y = pack2(ql[s], ql[s]);
            pts2[2 * i]     = e0;
            pts2[2 * i + 1] = e1;
        }
#pragma unroll
        for (int p = 0; p < NPAIR; p++) {
            nx2[p] = pack2(-lx[2 * p], -lx[2 * p + 1]);
            ny2[p] = pack2(-ly[2 * p], -ly[2 * p + 1]);
            nz2[p] = pack2(-lz[2 * p], -lz[2 * p + 1]);
            q2[p]  = pack2(ql[2 * p],  ql[2 * p + 1]);
        }
    }
    __syncthreads();

    // ---- Prim init (h = d^2/2 = q_s + q_j - p.pj) ----
    const unsigned VISITED = 0xFFFFFFFFu;

    unsigned pk[PPT];
    unsigned pmi[PPT];   // sticky mask: idx while alive, 0xFFFFFFFF once visited
#pragma unroll
    for (int s = 0; s < PPT; s++) pmi[s] = (unsigned)(tid + s * THREADS);

    {
        ulonglong2 exy = pts2[0], ezq = pts2[1];
#pragma unroll
        for (int p = 0; p < NPAIR; p++) {
            unsigned long long h2 = fma2(nx2[p], exy.x,
                                     fma2(ny2[p], exy.y,
                                       fma2(nz2[p], ezq.x, add2(q2[p], ezq.y))));
            unsigned hlo, hhi; unpack2u(hlo, hhi, h2);
            pk[2 * p]     = (hlo & PK_MASK) | pmi[2 * p];
            pk[2 * p + 1] = (hhi & PK_MASK) | pmi[2 * p + 1];
        }
    }
    if (tid == 0) {     // root visited
        pk[0]  = VISITED;
        pmi[0] = VISITED;
    }

    float total = 0.0f;   // accumulates h (= d^2/2); doubled at the end
    for (int it = 0; it < NPTS - 1; ++it) {
        const int buf = it & 1;

        // thread-local min: 3 IMNMX (depth 2); REDUX carries value AND index
        unsigned lm = um(um(pk[0], pk[1]), um(pk[2], pk[3]));
        unsigned wm = __reduce_min_sync(0xffffffffu, lm);
        if (lane == 0) s_pk[buf][wid] = wm;
        __syncthreads();   // one barrier per iteration (double-buffered)

        // cross-warp min: TWO LDS.128 + 7 IMNMX (depth 3)
        const uint4* q = reinterpret_cast<const uint4*>(s_pk[buf]);
        uint4 a = q[0], b = q[1];
        unsigned g = um(um(um(a.x, a.y), um(a.z, a.w)),
                        um(um(b.x, b.y), um(b.z, b.w)));

        total += __uint_as_float(g & PK_MASK);

        // broadcast fetch: two independent LDS.128, operands pre-duplicated
        int gj = (int)(g & 1023u);
        ulonglong2 exy = pts2[2 * gj];      // {x,x | y,y}
        ulonglong2 ezq = pts2[2 * gj + 1];  // {z,z | q,q}

        // mark visited: slot whose pk equals g (unique). pmi goes sticky-ones.
#pragma unroll
        for (int s = 0; s < PPT; s++) {
            if (pk[s] == g) { pk[s] = VISITED; pmi[s] = VISITED; }
        }

        // relax, packed: 2 points per 4 fma-pipe ops; cand self-poisons via pmi
#pragma unroll
        for (int p = 0; p < NPAIR; p++) {
            unsigned long long h2 = fma2(nx2[p], exy.x,
                                     fma2(ny2[p], exy.y,
                                       fma2(nz2[p], ezq.x, add2(q2[p], ezq.y))));
            unsigned hlo, hhi; unpack2u(hlo, hhi, h2);
            unsigned c0 = (hlo & PK_MASK) | pmi[2 * p];
            unsigned c1 = (hhi & PK_MASK) | pmi[2 * p + 1];
            pk[2 * p]     = um(pk[2 * p],     c0);
            pk[2 * p + 1] = um(pk[2 * p + 1], c1);
        }
    }

    // ---- deterministic finalize in the last-arriving CTA ----
    if (tid == 0) {
        g_partials[blockIdx.x] = total * 2.0f;   // h -> d^2
        __threadfence();
        unsigned t = atomicAdd(&g_ticket, 1u);
        s_last = (t == NPROB - 1);
    }
    __syncthreads();
    if (s_last && tid == 0) {
        __threadfence();
        float acc = 0.0f;
#pragma unroll
        for (int p = 0; p < NPROB; p++) acc += g_partials[p];
        out[0] = acc * (1.0f / NPROB);
        g_ticket = 0;   // reset for next graph replay
    }
}

extern "C" void kernel_launch(void* const* d_in, const int* in_sizes, int n_in,
                              void* d_out, int out_size)
{
    const float* r = (const float*)d_in[0];
    float* out = (float*)d_out;
    topo_mst_kernel<<<NPROB, THREADS>>>(r, out);
}

// round 15
// speedup vs baseline: 1.1350x; 1.1350x over previous
#include <cuda_runtime.h>
#include <math.h>

// Dataset-fixed shapes: r is [16, 2048, 3] fp32
#define NPTS    1024              // points per MST problem
#define NPROB   32                // independent MST problems
#define THREADS 128               // 4 warps: one per SMSP
#define PPT     (NPTS / THREADS)  // 8 points per thread
#define NPAIR   (PPT / 2)         // 4 f32x2 pairs per thread
#define NW      (THREADS / 32)    // 4 warps

__device__ float    g_partials[NPROB];
__device__ unsigned g_ticket;     // zero-init; last CTA resets for graph replay

__device__ __forceinline__ float warp_sum(float v) {
#pragma unroll
    for (int o = 16; o; o >>= 1) v += __shfl_xor_sync(0xffffffffu, v, o);
    return v;
}

__device__ __forceinline__ unsigned um(unsigned a, unsigned b) { return a < b ? a : b; }

// ---- packed f32x2 helpers (Blackwell FFMA2/FADD2 via PTX) ----
__device__ __forceinline__ unsigned long long pack2(float lo, float hi) {
    unsigned long long d;
    asm("mov.b64 %0, {%1, %2};" : "=l"(d) : "f"(lo), "f"(hi));
    return d;
}
__device__ __forceinline__ void unpack2u(unsigned& lo, unsigned& hi, unsigned long long v) {
    asm("mov.b64 {%0, %1}, %2;" : "=r"(lo), "=r"(hi) : "l"(v));
}
__device__ __forceinline__ unsigned long long add2(unsigned long long a, unsigned long long b) {
    unsigned long long d;
    asm("add.rn.f32x2 %0, %1, %2;" : "=l"(d) : "l"(a), "l"(b));
    return d;
}
__device__ __forceinline__ unsigned long long fma2(unsigned long long a, unsigned long long b,
                                                   unsigned long long c) {
    unsigned long long d;
    asm("fma.rn.f32x2 %0, %1, %2, %3;" : "=l"(d) : "l"(a), "l"(b), "l"(c));
    return d;
}

// Pack: high 22 bits = float bits of h = d^2/2 (low 10 mantissa bits truncated),
// low 10 bits = point index. Unsigned order == (h, idx) order (h >= 0).
// pk values are globally unique within a problem (index embedded).
#define PK_MASK 0xFFFFFC00u

__global__ __launch_bounds__(THREADS, 1)
void topo_mst_kernel(const float* __restrict__ r, float* __restrict__ out)
{
    // Pre-duplicated point data: entry 2i = {x,x | y,y}, 2i+1 = {z,z | q,q}.
    __shared__ ulonglong2 pts2[2 * NPTS];           // 32 KB
    __shared__ float redbuf[3][NW];
    __shared__ alignas(16) unsigned s_pk[2][NW];    // double-buffered warp mins
    __shared__ bool s_last;

    const int tid  = threadIdx.x;
    const int lane = tid & 31;
    const int wid  = tid >> 5;

    const float* base = r + (size_t)blockIdx.x * NPTS * 3;

    // ---- Load (thread t owns points t, t+128, ..., t+896) ----
    float lx[PPT], ly[PPT], lz[PPT];
    float sx = 0.f, sy = 0.f, sz = 0.f;
#pragma unroll
    for (int s = 0; s < PPT; s++) {
        int i = tid + s * THREADS;
        float x = base[3 * i + 0];
        float y = base[3 * i + 1];
        float z = base[3 * i + 2];
        lx[s] = x; ly[s] = y; lz[s] = z;
        sx += x; sy += y; sz += z;
    }

    // ---- Mean ----
    sx = warp_sum(sx); sy = warp_sum(sy); sz = warp_sum(sz);
    if (lane == 0) { redbuf[0][wid] = sx; redbuf[1][wid] = sy; redbuf[2][wid] = sz; }
    __syncthreads();
    float mx = 0.f, my = 0.f, mz = 0.f;
#pragma unroll
    for (int w = 0; w < NW; w++) { mx += redbuf[0][w]; my += redbuf[1][w]; mz += redbuf[2][w]; }
    mx *= (1.0f / NPTS); my *= (1.0f / NPTS); mz *= (1.0f / NPTS);
    __syncthreads();

    // ---- Variance ----
    float vx = 0.f, vy = 0.f, vz = 0.f;
#pragma unroll
    for (int s = 0; s < PPT; s++) {
        float dx = lx[s] - mx, dy = ly[s] - my, dz = lz[s] - mz;
        vx = fmaf(dx, dx, vx); vy = fmaf(dy, dy, vy); vz = fmaf(dz, dz, vz);
    }
    vx = warp_sum(vx); vy = warp_sum(vy); vz = warp_sum(vz);
    if (lane == 0) { redbuf[0][wid] = vx; redbuf[1][wid] = vy; redbuf[2][wid] = vz; }
    __syncthreads();
    vx = 0.f; vy = 0.f; vz = 0.f;
#pragma unroll
    for (int w = 0; w < NW; w++) { vx += redbuf[0][w]; vy += redbuf[1][w]; vz += redbuf[2][w]; }
    const float inx = 1.0f / (sqrtf(vx * (1.0f / NPTS)) + 1e-8f);
    const float iny = 1.0f / (sqrtf(vy * (1.0f / NPTS)) + 1e-8f);
    const float inz = 1.0f / (sqrtf(vz * (1.0f / NPTS)) + 1e-8f);

    // ---- Normalize; q = |p|^2/2; duplicated shared pairs; packed state ----
    unsigned long long nx2[NPAIR], ny2[NPAIR], nz2[NPAIR], q2[NPAIR];
    {
        float ql[PPT];
#pragma unroll
        for (int s = 0; s < PPT; s++) {
            int i = tid + s * THREADS;
            float x = (lx[s] - mx) * inx;
            float y = (ly[s] - my) * iny;
            float z = (lz[s] - mz) * inz;
            lx[s] = x; ly[s] = y; lz[s] = z;
            ql[s] = 0.5f * fmaf(x, x, fmaf(y, y, z * z));
            ulonglong2 e0, e1;
            e0.x = pack2(x, x);    e0.y = pack2(y, y);
            e1.x = pack2(z, z);    e1.y = pack2(ql[s], ql[s]);
            pts2[2 * i]     = e0;
            pts2[2 * i + 1] = e1;
        }
#pragma unroll
        for (int p = 0; p < NPAIR; p++) {
            nx2[p] = pack2(-lx[2 * p], -lx[2 * p + 1]);
            ny2[p] = pack2(-ly[2 * p], -ly[2 * p + 1]);
            nz2[p] = pack2(-lz[2 * p], -lz[2 * p + 1]);
            q2[p]  = pack2(ql[2 * p],  ql[2 * p + 1]);   // immutable from here on
        }
    }
    __syncthreads();

    // ---- Prim init (h = d^2/2 = q_s + q_j - p.pj) ----
    const unsigned VISITED = 0xFFFFFFFFu;

    unsigned pk[PPT];
    unsigned pmi[PPT];   // sticky mask: idx while alive, 0xFFFFFFFF once visited
#pragma unroll
    for (int s = 0; s < PPT; s++) pmi[s] = (unsigned)(tid + s * THREADS);

    {
        ulonglong2 exy = pts2[0], ezq = pts2[1];   // point 0 duplicated pairs
#pragma unroll
        for (int p = 0; p < NPAIR; p++) {
            unsigned long long h2 = fma2(nx2[p], exy.x,
                                     fma2(ny2[p], exy.y,
                                       fma2(nz2[p], ezq.x, add2(q2[p], ezq.y))));
            unsigned hlo, hhi; unpack2u(hlo, hhi, h2);
            pk[2 * p]     = (hlo & PK_MASK) | pmi[2 * p];
            pk[2 * p + 1] = (hhi & PK_MASK) | pmi[2 * p + 1];
        }
    }
    if (tid == 0) {     // root visited: sticky mask forces cand = 0xFFFFFFFF
        pk[0]  = VISITED;
        pmi[0] = VISITED;
    }

    float total = 0.0f;   // accumulates h (= d^2/2); doubled at the end

    // one Prim selection round; BUF is a compile-time 0/1 (double buffering)
    auto prim_step = [&](const int BUF) {
        // thread-local min: 7 IMNMX (depth 3); REDUX carries value AND index
        unsigned m0 = um(pk[0], pk[1]), m1 = um(pk[2], pk[3]);
        unsigned m2 = um(pk[4], pk[5]), m3 = um(pk[6], pk[7]);
        unsigned lm = um(um(m0, m1), um(m2, m3));
        unsigned wm = __reduce_min_sync(0xffffffffu, lm);
        if (lane == 0) s_pk[BUF][wid] = wm;
        __syncthreads();   // one barrier per round (double-buffered)

        // cross-warp min: ONE LDS.128 + 3 IMNMX (depth 2)
        uint4 a = *reinterpret_cast<const uint4*>(s_pk[BUF]);
        unsigned g = um(um(a.x, a.y), um(a.z, a.w));

        total += __uint_as_float(g & PK_MASK);

        // broadcast fetch: two independent LDS.128, operands pre-duplicated
        int gj = (int)(g & 1023u);
        ulonglong2 exy = pts2[2 * gj];      // {x,x | y,y}
        ulonglong2 ezq = pts2[2 * gj + 1];  // {z,z | q,q}

        // mark visited: slot whose pk equals g (unique). pmi goes sticky-ones.
#pragma unroll
        for (int s = 0; s < PPT; s++) {
            if (pk[s] == g) { pk[s] = VISITED; pmi[s] = VISITED; }
        }

        // relax, packed: 2 points per 4 fma-pipe ops; cand self-poisons via pmi
#pragma unroll
        for (int p = 0; p < NPAIR; p++) {
            unsigned long long h2 = fma2(nx2[p], exy.x,
                                     fma2(ny2[p], exy.y,
                                       fma2(nz2[p], ezq.x, add2(q2[p], ezq.y))));
            unsigned hlo, hhi; unpack2u(hlo, hhi, h2);
            unsigned c0 = (hlo & PK_MASK) | pmi[2 * p];
            unsigned c1 = (hhi & PK_MASK) | pmi[2 * p + 1];
            pk[2 * p]     = um(pk[2 * p],     c0);
            pk[2 * p + 1] = um(pk[2 * p + 1], c1);
        }
    };

    // 1023 rounds = 511 unrolled pairs + 1 (buffers alternate 0,1,0,1,...,0)
    for (int it = 0; it < (NPTS - 1) / 2; ++it) {
        prim_step(0);
        prim_step(1);
    }
    prim_step(0);

    // ---- deterministic finalize in the last-arriving CTA ----
    if (tid == 0) {
        g_partials[blockIdx.x] = total * 2.0f;   // h -> d^2
        __threadfence();
        unsigned t = atomicAdd(&g_ticket, 1u);
        s_last = (t == NPROB - 1);
    }
    __syncthreads();
    if (s_last && tid == 0) {
        __threadfence();
        float acc = 0.0f;
#pragma unroll
        for (int p = 0; p < NPROB; p++) acc += g_partials[p];
        out[0] = acc * (1.0f / NPROB);
        g_ticket = 0;   // reset for next graph replay
    }
}

extern "C" void kernel_launch(void* const* d_in, const int* in_sizes, int n_in,
                              void* d_out, int out_size)
{
    const float* r = (const float*)d_in[0];
    float* out = (float*)d_out;
    topo_mst_kernel<<<NPROB, THREADS>>>(r, out);
}